// round 17
// baseline (speedup 1.0000x reference)
#include <cuda_runtime.h>
#include <math.h>

// Preisach hysteresis (R16): ONE kernel, one grid barrier.
//   state row j = prefix of +1 of length c_j, then -1 (within lower triangle).
//   up-step h:   rows with x[j] < h  -> c_j = j+1
//   down-step h: all rows            -> c_j = min(c_j, K), K = #{k: x[k] <= h}
//   b[t] = (sum_j (2*P_j(c_j) - RowTot_j)) / 32896 * scale + offset
// Function encode: SET(v) = 512+v, MIN(m) = m (m <= 511; MIN(511) = identity).
// P1: CTAs 0-7 row prefix sums (one warp/row); CTAs 8-87 meta + chunk
//     functions g_fv[ci][j]; CTAs 88-124 idle.
// barrier (single, busy-spin, replay-safe monotonic flag)
// P2: every CTA: 4-way split entry scan (20 chunks/thread), smem merge,
//     16 emit warps replay within-chunk prefix, Li gather + REDUX.

#define NN 256
#define TT 2000
#define CHUNK 25
#define NCHUNK 80
#define NB 125
#define QSCALE 8192.0f

__device__ int g_Li[NN * (NN + 1) / 2 + NN];   // row-local prefix sums (quantized)
__device__ int g_RowTotI[NN];
__device__ int g_meta[TT];                      // -1 up, -2 flat, else K (down)
__device__ int g_fv[NCHUNK * NN];               // [chunk][row] chunk functions

__device__ unsigned g_barflag = 0;   // monotonically increasing across replays
__device__ int      g_barcnt  = 0;   // self-resetting arrival counter

__device__ __forceinline__ float xval(int i) {
    // replicate jnp.linspace(0,1,256) in f32: i * fl(1/255), endpoint exact
    return (i == NN - 1) ? 1.0f : (float)i * (1.0f / 255.0f);
}
__device__ __forceinline__ float softplusf(float v) {
    return fmaxf(v, 0.0f) + log1pf(expf(-fabsf(v)));
}
// K = #{k in [0,256): xval(k) <= hc}; xval weakly monotone -> branchless
// binary search with the identical '<=' predicate (hc<1 on down-steps).
__device__ __forceinline__ int count_le(float hc) {
    int K = 0;
    #pragma unroll
    for (int s = 128; s > 0; s >>= 1) {
        int cand = K + s;
        if (xval(cand - 1) <= hc) K = cand;
    }
    return K;
}
// apply encoded function to a state
__device__ __forceinline__ int fapply(int enc, int c) {
    return (enc >= 512) ? (enc - 512) : min(c, enc);
}

__global__ void __launch_bounds__(1024, 1)
fused(const float* __restrict__ raw, const float* __restrict__ h,
      const float* __restrict__ offset, const float* __restrict__ scale,
      float* __restrict__ out) {
    __shared__ int   sV[256], sF1[256], sF2[256], sF3[256];
    __shared__ int   sE0[256], sE1[256];
    __shared__ int   stot[8];
    __shared__ int   smeta[2 * CHUNK];
    __shared__ float shh[2 * CHUNK];
    __shared__ int   sm1[CHUNK];
    __shared__ float sh1[CHUNK];

    int tid = threadIdx.x;
    int bx  = blockIdx.x;

    unsigned base = 0;
    if (tid == 0) base = *(volatile unsigned*)&g_barflag;

    // ================= Phase 1 =================
    if (bx < 8) {
        // row prefix sums of softplus(raw): warp per row, rows bx*32+wid
        int wid  = tid >> 5;
        int lane = tid & 31;
        int j  = bx * 32 + wid;
        int sj = j * (j + 1) / 2;
        int oj = sj + j;
        int n  = j + 1;

        int b8 = lane * 8;
        float v[8];
        #pragma unroll
        for (int k = 0; k < 8; k++) {
            int idx = b8 + k;
            v[k] = (idx < n) ? raw[sj + idx] : 0.0f;
        }
        int loc[8];
        int run = 0;
        #pragma unroll
        for (int k = 0; k < 8; k++) {
            int idx = b8 + k;
            int q = (idx < n) ? __float2int_rn(softplusf(v[k]) * QSCALE) : 0;
            run += q;
            loc[k] = run;
        }
        int excl = run;
        #pragma unroll
        for (int d = 1; d < 32; d <<= 1) {
            int t = __shfl_up_sync(0xffffffffu, excl, d);
            if (lane >= d) excl += t;
        }
        excl -= run;

        if (lane == 0) g_Li[oj] = 0;
        #pragma unroll
        for (int k = 0; k < 8; k++) {
            int idx = b8 + k;
            if (idx < n) g_Li[oj + 1 + idx] = excl + loc[k];
        }
        if (lane == 31) g_RowTotI[j] = excl + run;
    } else if (bx < 88) {
        // per-step meta + per-(chunk,row) chunk function
        int ci = bx - 8;
        int t0 = ci * CHUNK;
        if (tid < CHUNK) {
            int t = t0 + tid;
            float hp = (t == 0) ? 0.0f : h[t - 1];
            float hc = h[t];
            int m;
            if (hc > hp)       m = -1;
            else if (hc < hp)  m = count_le(hc);
            else               m = -2;
            sm1[tid] = m; sh1[tid] = hc;
            g_meta[t] = m;
        }
        __syncthreads();
        if (tid < NN) {
            float xj = xval(tid);
            bool isC = false;
            int vv = 0, m = 511;
            #pragma unroll
            for (int s = 0; s < CHUNK; s++) {
                int mt = sm1[s];
                if (mt == -1) {
                    if (xj < sh1[s]) { isC = true; vv = tid + 1; }
                } else if (mt >= 0) {
                    if (isC) vv = min(vv, mt); else m = min(m, mt);
                }
            }
            g_fv[ci * NN + tid] = isC ? (512 + vv) : m;
        }
    }

    // ================= Barrier (single, busy-spin) =================
    __syncthreads();
    if (tid == 0) {
        __threadfence();                         // release phase-1 writes
        int v = atomicAdd(&g_barcnt, 1);
        if (v == NB - 1) {
            g_barcnt = 0;
            __threadfence();
            *(volatile unsigned*)&g_barflag = base + 1;
        } else {
            while (*(volatile unsigned*)&g_barflag - base < 1u) { }
        }
        __threadfence();                         // acquire
    }
    __syncthreads();

    // ================= Phase 2: emit =================
    int blockBase = bx * 16;
    int ci0 = blockBase / CHUNK;
    int t0base = ci0 * CHUNK;

    // stage meta/h for this CTA's <=2 chunks
    if (tid < 2 * CHUNK) {
        int tt = t0base + tid;
        if (tt < TT) { smeta[tid] = g_meta[tt]; shh[tid] = h[tt]; }
    }

    // chunk-ci0 function for entry(ci0+1) derivation (threads 0-255)
    int gc = 0;
    if (tid < 256) gc = g_fv[ci0 * NN + tid];
    int rt = (tid < 256) ? g_RowTotI[tid] : 0;

    // 4-way split entry scan: seg in {0..3}, 20 chunks each
    {
        int seg  = tid >> 8;
        int jrow = tid & 255;
        int cb   = seg * 20;
        int fv[20];
        #pragma unroll
        for (int i = 0; i < 20; i++) fv[i] = g_fv[(cb + i) * NN + jrow];

        if (seg == 0) {
            int c = 0;
            #pragma unroll
            for (int i = 0; i < 20; i++) {
                int nc = fapply(fv[i], c);
                c = (i < ci0) ? nc : c;
            }
            sV[jrow] = c;
        } else {
            int enc = 511;                       // identity MIN
            #pragma unroll
            for (int i = 0; i < 20; i++) {
                int fs = fv[i];
                int ne = (fs >= 512) ? fs
                       : ((enc >= 512) ? (512 + min(enc - 512, fs))
                                       : min(enc, fs));
                enc = (cb + i < ci0) ? ne : enc;
            }
            if (seg == 1) sF1[jrow] = enc;
            else if (seg == 2) sF2[jrow] = enc;
            else sF3[jrow] = enc;
        }
    }
    // total reduce (rows counted once by threads 0-255 = warps 0-7)
    {
        int ws = __reduce_add_sync(0xffffffffu, rt);
        if (tid < 256 && (tid & 31) == 0) stot[tid >> 5] = ws;
    }
    __syncthreads();

    // merge to per-row entries (threads 0-255)
    if (tid < 256) {
        int e = fapply(sF3[tid], fapply(sF2[tid], fapply(sF1[tid], sV[tid])));
        sE0[tid] = e;
        sE1[tid] = fapply(gc, e);                // entry(ci0+1)
    }
    __syncthreads();

    // emit: warps 0-15, one warp per output step
    if (tid < 512) {
        int wid  = tid >> 5;
        int lane = tid & 31;
        int t  = blockBase + wid;
        int ci = t / CHUNK;
        int tc0 = ci * CHUNK;
        int nst = t - tc0 + 1;                   // 1..25 steps to replay
        int lu0 = (ci - ci0) * CHUNK;

        int totalI = 0;
        #pragma unroll
        for (int w = 0; w < 8; w++) totalI += stot[w];

        const int* E = (ci == ci0) ? sE0 : sE1;
        int c[8], oj[8];
        float xq[8];
        #pragma unroll
        for (int q = 0; q < 8; q++) {
            int j = lane + 32 * q;
            oj[q] = j * (j + 3) / 2;
            xq[q] = xval(j);
            c[q]  = E[j];
        }

        for (int u = 0; u < nst; u++) {
            int   mt = smeta[lu0 + u];
            float hc = shh[lu0 + u];
            if (mt == -1) {
                #pragma unroll
                for (int q = 0; q < 8; q++) {
                    int j = lane + 32 * q;
                    if (xq[q] < hc) c[q] = j + 1;
                }
            } else if (mt >= 0) {
                #pragma unroll
                for (int q = 0; q < 8; q++) c[q] = min(c[q], mt);
            }
        }

        int rv[8];
        #pragma unroll
        for (int q = 0; q < 8; q++) rv[q] = g_Li[oj[q] + c[q]]; // 8 parallel LDG

        int s8 = ((rv[0] + rv[1]) + (rv[2] + rv[3])) +
                 ((rv[4] + rv[5]) + (rv[6] + rv[7]));
        int tot = __reduce_add_sync(0xffffffffu, s8);

        if (lane == 0) {
            float numer = (float)(2 * tot - totalI) * (1.0f / QSCALE);
            out[t] = numer * (1.0f / 32896.0f) * scale[0] + offset[0];
        }
    }
}

extern "C" void kernel_launch(void* const* d_in, const int* in_sizes, int n_in,
                              void* d_out, int out_size) {
    const float* h      = (const float*)d_in[0];
    const float* raw    = (const float*)d_in[1];
    const float* offset = (const float*)d_in[2];
    const float* scale  = (const float*)d_in[3];
    float* out = (float*)d_out;

    fused<<<NB, 1024>>>(raw, h, offset, scale, out);
}